// round 5
// baseline (speedup 1.0000x reference)
#include <cuda_runtime.h>
#include <cuda_bf16.h>
#include <math.h>

#define BATCH 4096
#define NNB   64
#define DM    256
#define NH    8
#define HD    32
#define SCALE 0.17677669529663687f   // 1/sqrt(32)
#define NBS   260                    // nb smem row stride (floats)

// ---------------- scratch ----------------
__device__ float d_Q  [BATCH * DM];
__device__ float d_U  [BATCH * NH * DM];
__device__ float d_ctx[BATCH * NH * DM];
__device__ float d_att[BATCH * DM];
__device__ float d_y  [BATCH * DM];
__device__ float d_WkT[NH * DM * HD];      // [h][c][d]
__device__ float d_WoT[DM * DM];
__device__ float d_Wc [DM * DM];
__device__ float d_b1 [DM];
__device__ unsigned int d_or = 0u;         // OR of odd words; 0 => int64 (idempotent)

// ---------------- prep: transposes + b1 + edge-dtype detect ----------------
__global__ void prep_kernel(const float* __restrict__ Wk,
                            const float* __restrict__ Wo,
                            const float* __restrict__ Wf,
                            const float* __restrict__ bo,
                            const float* __restrict__ bfv,
                            const unsigned int* __restrict__ e32) {
    const int blk = blockIdx.x, t = threadIdx.x;
    const int i = blk * 256 + t;                 // 0..65535
    { int dd = i & 31, c = (i >> 5) & 255, h = i >> 13;
      d_WkT[i] = Wk[(h * HD + dd) * DM + c]; }
    { int j = i >> 8, m = i & 255;
      d_WoT[i] = Wo[m * DM + j]; }
    if (blk < 32) {                              // b1: warp per output
        int o = blk * 8 + (t >> 5), l = t & 31;
        float s = 0.f;
        #pragma unroll
        for (int m = l; m < DM; m += 32) s += Wf[o * 2 * DM + m] * bo[m];
        #pragma unroll
        for (int off = 16; off; off >>= 1) s += __shfl_xor_sync(0xffffffffu, s, off);
        if (l == 0) d_b1[o] = bfv[o] + s;
    }
    // edge dtype: OR all odd 32-bit words of the edge buffer (int64 -> all zero)
    unsigned int acc = 0u;
    #pragma unroll
    for (int w = i; w < BATCH * NNB; w += 65536) acc |= e32[2 * w + 1];
    #pragma unroll
    for (int o = 16; o; o >>= 1) acc |= __shfl_xor_sync(0xffffffffu, acc, o);
    __shared__ unsigned int sOr;
    if (t == 0) sOr = 0u;
    __syncthreads();
    if ((t & 31) == 0 && acc) atomicOr(&sOr, acc);
    __syncthreads();
    if (t == 0 && sOr) atomicOr(&d_or, sOr);
}

// ---------------- dedicated U GEMM ----------------
// U[b, h*256+c] = SCALE * sum_d Q[b, h*32+d] * WkT[h][c][d]
// CTA: 128 rows x 128 cols x 1 head. 256 threads, TM=TN=8, stride-16 ownership.
__global__ __launch_bounds__(256) void ugemm_kernel() {
    __shared__ float As[HD][132];   // [d][row]
    __shared__ float Bs[HD][132];   // [d][col]
    const int t = threadIdx.x;
    const int tx = t & 15, ty = t >> 4;
    const int b0 = blockIdx.y * 128;
    const int c0 = blockIdx.x * 128;
    const int h  = blockIdx.z;

    // stage Q tile [128 rows][32 d] transposed
    #pragma unroll
    for (int i = 0; i < 4; i++) {
        int f = t + i * 256;             // 0..1023
        int r = f >> 3, dq = f & 7;
        float4 v = *reinterpret_cast<const float4*>(d_Q + (long)(b0 + r) * DM + h * HD + dq * 4);
        As[dq * 4 + 0][r] = v.x; As[dq * 4 + 1][r] = v.y;
        As[dq * 4 + 2][r] = v.z; As[dq * 4 + 3][r] = v.w;
    }
    // stage WkT tile [128 cols][32 d] transposed
    #pragma unroll
    for (int i = 0; i < 4; i++) {
        int f = t + i * 256;
        int c = f >> 3, dq = f & 7;
        float4 v = *reinterpret_cast<const float4*>(d_WkT + h * (DM * HD) + (c0 + c) * HD + dq * 4);
        Bs[dq * 4 + 0][c] = v.x; Bs[dq * 4 + 1][c] = v.y;
        Bs[dq * 4 + 2][c] = v.z; Bs[dq * 4 + 3][c] = v.w;
    }
    __syncthreads();

    float acc[8][8];
    #pragma unroll
    for (int i = 0; i < 8; i++)
        #pragma unroll
        for (int j = 0; j < 8; j++) acc[i][j] = 0.f;

    #pragma unroll
    for (int d = 0; d < HD; d++) {
        float a[8], b[8];
        #pragma unroll
        for (int i = 0; i < 8; i++) a[i] = As[d][ty + 16 * i];
        #pragma unroll
        for (int j = 0; j < 8; j++) b[j] = Bs[d][tx + 16 * j];
        #pragma unroll
        for (int i = 0; i < 8; i++)
            #pragma unroll
            for (int j = 0; j < 8; j++) acc[i][j] += a[i] * b[j];
    }

    #pragma unroll
    for (int i = 0; i < 8; i++) {
        long base = (long)(b0 + ty + 16 * i) * (NH * DM) + h * DM + c0;
        #pragma unroll
        for (int j = 0; j < 8; j++)
            d_U[base + tx + 16 * j] = SCALE * acc[i][j];
    }
}

// ---------------- double-buffered NT GEMM with optional dual K-source -------
template<int BM, int BN, int TM, int TN>
__global__ void gemm2_kernel(const float* __restrict__ A1, int lda1, long az1,
                             const float* __restrict__ B1, int ldb1, long bz1,
                             const float* __restrict__ A2, int lda2,
                             const float* __restrict__ B2, int ldb2,
                             const float* __restrict__ bias, long biasz,
                             float* __restrict__ C, int ldc, long cz,
                             int K1, int Ktot, float alpha) {
    constexpr int BK = 16;
    constexpr int NT = (BM / TM) * (BN / TN);
    constexpr int PAD = 4;
    constexpr int A4 = BM * BK / 4;
    constexpr int B4 = BN * BK / 4;
    constexpr int NA = (A4 + NT - 1) / NT;
    constexpr int NB = (B4 + NT - 1) / NT;

    __shared__ float As[2][BK][BM + PAD];
    __shared__ float Bs[2][BK][BN + PAD];

    const int tid = threadIdx.x;
    const int tx = tid % (BN / TN);
    const int ty = tid / (BN / TN);
    const int row0 = blockIdx.y * BM;
    const int col0 = blockIdx.x * BN;
    const int z = blockIdx.z;

    const float* A1g = A1 + (long)z * az1;
    const float* B1g = B1 + (long)z * bz1;
    float* Cg = C + (long)z * cz;
    const float* biasg = bias ? bias + (long)z * biasz : nullptr;

    float4 ra[NA], rb[NB];

    auto fetch = [&](int t) {
        int k0 = t * BK;
        const float *Ap, *Bp; int lda, ldb, k;
        if (k0 < K1) { Ap = A1g; lda = lda1; Bp = B1g; ldb = ldb1; k = k0; }
        else         { Ap = A2;  lda = lda2; Bp = B2;  ldb = ldb2; k = k0 - K1; }
        #pragma unroll
        for (int i = 0; i < NA; i++) {
            int f = tid + i * NT;
            if (f < A4) {
                int r = f >> 2, kq = f & 3;
                ra[i] = *reinterpret_cast<const float4*>(Ap + (long)(row0 + r) * lda + k + kq * 4);
            }
        }
        #pragma unroll
        for (int i = 0; i < NB; i++) {
            int f = tid + i * NT;
            if (f < B4) {
                int n = f >> 2, kq = f & 3;
                rb[i] = *reinterpret_cast<const float4*>(Bp + (long)(col0 + n) * ldb + k + kq * 4);
            }
        }
    };
    auto stage = [&](int buf) {
        #pragma unroll
        for (int i = 0; i < NA; i++) {
            int f = tid + i * NT;
            if (f < A4) {
                int r = f >> 2, kq = f & 3;
                As[buf][kq * 4 + 0][r] = ra[i].x;
                As[buf][kq * 4 + 1][r] = ra[i].y;
                As[buf][kq * 4 + 2][r] = ra[i].z;
                As[buf][kq * 4 + 3][r] = ra[i].w;
            }
        }
        #pragma unroll
        for (int i = 0; i < NB; i++) {
            int f = tid + i * NT;
            if (f < B4) {
                int n = f >> 2, kq = f & 3;
                Bs[buf][kq * 4 + 0][n] = rb[i].x;
                Bs[buf][kq * 4 + 1][n] = rb[i].y;
                Bs[buf][kq * 4 + 2][n] = rb[i].z;
                Bs[buf][kq * 4 + 3][n] = rb[i].w;
            }
        }
    };

    float acc[TM][TN];
    #pragma unroll
    for (int i = 0; i < TM; i++)
        #pragma unroll
        for (int j = 0; j < TN; j++) acc[i][j] = 0.f;

    fetch(0); stage(0); __syncthreads();
    const int ntiles = Ktot / BK;
    for (int t = 0; t < ntiles; t++) {
        int cur = t & 1;
        if (t + 1 < ntiles) fetch(t + 1);
        #pragma unroll
        for (int kk = 0; kk < BK; kk++) {
            float a[TM], b[TN];
            #pragma unroll
            for (int i = 0; i < TM; i++) a[i] = As[cur][kk][ty * TM + i];
            #pragma unroll
            for (int j = 0; j < TN; j++) b[j] = Bs[cur][kk][tx * TN + j];
            #pragma unroll
            for (int i = 0; i < TM; i++)
                #pragma unroll
                for (int j = 0; j < TN; j++) acc[i][j] += a[i] * b[j];
        }
        if (t + 1 < ntiles) stage(cur ^ 1);
        __syncthreads();
    }

    #pragma unroll
    for (int i = 0; i < TM; i++) {
        int r = row0 + ty * TM + i;
        #pragma unroll
        for (int j = 0; j < TN; j++) {
            int c = col0 + tx * TN + j;
            float v = alpha * acc[i][j];
            if (biasg) v += biasg[c];
            Cg[(long)r * ldc + c] = v;
        }
    }
}

// ---------------- fused attention (float4, one CTA per batch row) ------------
#define ATTN_SMEM_FLOATS (NNB * NBS + 2048 + 2048 + 512 + 512 + 64 + 8)
#define ATTN_SMEM_BYTES  (ATTN_SMEM_FLOATS * 4 + NNB * 4)

__global__ void attn_kernel(const float* __restrict__ nb,
                            const unsigned int* __restrict__ e32,
                            const float* __restrict__ ebt,
                            const float* __restrict__ bk) {
    extern __shared__ float sm[];
    float* nb_s  = sm;                       // 64*260
    float* u_s   = nb_s + NNB * NBS;         // 2048
    float* part  = u_s + 2048;               // 2048  [h*256 + q*64 + n]
    float* logit = part + 2048;              // 512
    float* attn_s= logit + 512;              // 512
    float* tbl   = attn_s + 512;             // 64
    float* kb_s  = tbl + 64;                 // 8
    int*   et_s  = (int*)(kb_s + 8);         // 64

    const int b = blockIdx.x;
    const int t = threadIdx.x;

    const float4* nbg = (const float4*)(nb + (long)b * NNB * DM);
    #pragma unroll
    for (int i = 0; i < 16; i++) {
        int f = t + i * 256;
        int row = f >> 6, c4 = f & 63;
        *reinterpret_cast<float4*>(nb_s + row * NBS + c4 * 4) = nbg[f];
    }
    const float4* ug = (const float4*)(d_U + (long)b * 2048);
    *reinterpret_cast<float4*>(u_s + t * 4)        = ug[t];
    *reinterpret_cast<float4*>(u_s + 1024 + t * 4) = ug[256 + t];
    if (t < NNB) {
        int ef = (d_or == 0u);
        int v = ef ? (int)e32[(long)b * (2 * NNB) + 2 * t]
                   : (int)e32[(long)b * NNB + t];
        et_s[t] = v;
        tbl[t] = ebt[t];
    }
    {
        const int w = t >> 5, l = t & 31;
        float s = d_Q[(long)b * DM + w * HD + l] * bk[w * HD + l];
        #pragma unroll
        for (int o = 16; o; o >>= 1) s += __shfl_xor_sync(0xffffffffu, s, o);
        if (l == 0) kb_s[w] = SCALE * s;
    }
    __syncthreads();

    {
        const int n = t & 63, q = t >> 6;
        const float* xr = nb_s + n * NBS + q * 64;
        const float* ur = u_s + q * 64;
        float acc[NH];
        #pragma unroll
        for (int h = 0; h < NH; h++) acc[h] = 0.f;
        #pragma unroll 4
        for (int c = 0; c < 64; c += 4) {
            float4 x = *reinterpret_cast<const float4*>(xr + c);
            #pragma unroll
            for (int h = 0; h < NH; h++) {
                float4 u = *reinterpret_cast<const float4*>(ur + h * DM + c);
                acc[h] += u.x * x.x + u.y * x.y + u.z * x.z + u.w * x.w;
            }
        }
        #pragma unroll
        for (int h = 0; h < NH; h++) part[h * 256 + q * 64 + n] = acc[h];
    }
    __syncthreads();

    #pragma unroll
    for (int idx = t; idx < NH * NNB; idx += 256) {
        int h = idx >> 6, n = idx & 63;
        float l = kb_s[h] + tbl[et_s[n] * NH + h];
        #pragma unroll
        for (int q = 0; q < 4; q++) l += part[h * 256 + q * 64 + n];
        logit[h * 64 + n] = l;
    }
    __syncthreads();

    {
        const int w = t >> 5, l = t & 31;
        float v1 = logit[w * 64 + l];
        float v2 = logit[w * 64 + 32 + l];
        float m = fmaxf(v1, v2);
        #pragma unroll
        for (int o = 16; o; o >>= 1) m = fmaxf(m, __shfl_xor_sync(0xffffffffu, m, o));
        float e1 = __expf(v1 - m), e2 = __expf(v2 - m);
        float s = e1 + e2;
        #pragma unroll
        for (int o = 16; o; o >>= 1) s += __shfl_xor_sync(0xffffffffu, s, o);
        float inv = 1.f / s;
        attn_s[w * 64 + l]      = e1 * inv;
        attn_s[w * 64 + 32 + l] = e2 * inv;
    }
    __syncthreads();

    {
        const int c4 = t & 63, hp = t >> 6;
        const float* colp = nb_s + c4 * 4;
        const float* a0p = attn_s + hp * 64;
        const float* a1p = attn_s + (hp + 4) * 64;
        float4 a0 = {0.f, 0.f, 0.f, 0.f};
        float4 a1 = {0.f, 0.f, 0.f, 0.f};
        #pragma unroll 8
        for (int n = 0; n < NNB; n++) {
            float4 x = *reinterpret_cast<const float4*>(colp + n * NBS);
            float w0 = a0p[n], w1 = a1p[n];
            a0.x += w0 * x.x; a0.y += w0 * x.y; a0.z += w0 * x.z; a0.w += w0 * x.w;
            a1.x += w1 * x.x; a1.y += w1 * x.y; a1.z += w1 * x.z; a1.w += w1 * x.w;
        }
        float4* cg = (float4*)(d_ctx + (long)b * 2048);
        cg[hp * 64 + c4]       = a0;
        cg[(hp + 4) * 64 + c4] = a1;
    }
}

// ---------------- LayerNorm + ReLU (warp per row, float4) ----------------
__global__ void ln_relu_kernel(const float* __restrict__ g,
                               const float* __restrict__ be,
                               float* __restrict__ out) {
    const int b = blockIdx.x * 8 + (threadIdx.x >> 5);
    const int l = threadIdx.x & 31;
    const float4* yr = (const float4*)(d_y + (long)b * DM) + l * 2;
    float4 v0 = yr[0], v1 = yr[1];
    float s = v0.x + v0.y + v0.z + v0.w + v1.x + v1.y + v1.z + v1.w;
    #pragma unroll
    for (int o = 16; o; o >>= 1) s += __shfl_xor_sync(0xffffffffu, s, o);
    float mu = s * (1.f / 256.f);
    float vs = 0.f;
    {
        float d;
        d = v0.x - mu; vs += d * d;  d = v0.y - mu; vs += d * d;
        d = v0.z - mu; vs += d * d;  d = v0.w - mu; vs += d * d;
        d = v1.x - mu; vs += d * d;  d = v1.y - mu; vs += d * d;
        d = v1.z - mu; vs += d * d;  d = v1.w - mu; vs += d * d;
    }
    #pragma unroll
    for (int o = 16; o; o >>= 1) vs += __shfl_xor_sync(0xffffffffu, vs, o);
    float r = rsqrtf(vs * (1.f / 256.f) + 1e-5f);
    const float4* gp = (const float4*)g + l * 2;
    const float4* bp = (const float4*)be + l * 2;
    float4* op = (float4*)(out + (long)b * DM) + l * 2;
    float4 g0 = gp[0], g1 = gp[1], b0 = bp[0], b1 = bp[1];
    float4 o0, o1;
    o0.x = fmaxf((v0.x - mu) * r * g0.x + b0.x, 0.f);
    o0.y = fmaxf((v0.y - mu) * r * g0.y + b0.y, 0.f);
    o0.z = fmaxf((v0.z - mu) * r * g0.z + b0.z, 0.f);
    o0.w = fmaxf((v0.w - mu) * r * g0.w + b0.w, 0.f);
    o1.x = fmaxf((v1.x - mu) * r * g1.x + b1.x, 0.f);
    o1.y = fmaxf((v1.y - mu) * r * g1.y + b1.y, 0.f);
    o1.z = fmaxf((v1.z - mu) * r * g1.z + b1.z, 0.f);
    o1.w = fmaxf((v1.w - mu) * r * g1.w + b1.w, 0.f);
    op[0] = o0; op[1] = o1;
}

// ---------------- host launcher ----------------
extern "C" void kernel_launch(void* const* d_in, const int* in_sizes, int n_in,
                              void* d_out, int out_size) {
    const float* cde = (const float*)d_in[0];
    const float* nb  = (const float*)d_in[1];
    const unsigned int* et = (const unsigned int*)d_in[2];
    const float* Wq = (const float*)d_in[3];
    const float* bq = (const float*)d_in[4];
    const float* Wk = (const float*)d_in[5];
    const float* bk = (const float*)d_in[6];
    const float* Wv = (const float*)d_in[7];
    const float* bv = (const float*)d_in[8];
    const float* Wo = (const float*)d_in[9];
    const float* bo = (const float*)d_in[10];
    const float* ebt = (const float*)d_in[11];
    const float* Wf = (const float*)d_in[12];
    const float* bfv = (const float*)d_in[13];
    const float* lg = (const float*)d_in[14];
    const float* lb = (const float*)d_in[15];
    float* out = (float*)d_out;

    float *pQ, *pCtx, *pAtt, *pY, *pWoT, *pWc, *pB1;
    cudaGetSymbolAddress((void**)&pQ,   d_Q);
    cudaGetSymbolAddress((void**)&pCtx, d_ctx);
    cudaGetSymbolAddress((void**)&pAtt, d_att);
    cudaGetSymbolAddress((void**)&pY,   d_y);
    cudaGetSymbolAddress((void**)&pWoT, d_WoT);
    cudaGetSymbolAddress((void**)&pWc,  d_Wc);
    cudaGetSymbolAddress((void**)&pB1,  d_b1);

    cudaFuncSetAttribute(attn_kernel,
                         cudaFuncAttributeMaxDynamicSharedMemorySize,
                         ATTN_SMEM_BYTES);

    // 1) prep (transposes + b1 + edge detect)
    prep_kernel<<<256, 256>>>(Wk, Wo, Wf, bo, bfv, et);
    // 2) Q = cde @ Wq^T + bq
    gemm2_kernel<64, 64, 8, 4><<<dim3(DM / 64, BATCH / 64, 1), 128>>>(
        cde, DM, 0, Wq, DM, 0, nullptr, 0, nullptr, 0,
        bq, 0, pQ, DM, 0, DM, DM, 1.f);
    // 3) U (dedicated kernel, K=32 single pass)
    ugemm_kernel<<<dim3(2, BATCH / 128, NH), 256>>>();
    // 4) fused attention  (launch #4 -> ncu capture target)
    attn_kernel<<<BATCH, 256, ATTN_SMEM_BYTES>>>(nb, et, ebt, bk);
    // 5) Wc = Wf[:, :256] @ Wo
    gemm2_kernel<64, 64, 8, 4><<<dim3(DM / 64, DM / 64, 1), 128>>>(
        Wf, 2 * DM, 0, pWoT, DM, 0, nullptr, 0, nullptr, 0,
        nullptr, 0, pWc, DM, 0, DM, DM, 1.f);
    // 6) att[b, h*32+d] = Wv_h[d,:].ctx[b,h,:] + bv
    gemm2_kernel<128, 32, 8, 2><<<dim3(1, BATCH / 128, NH), 256>>>(
        pCtx, NH * DM, DM, Wv, DM, (long)HD * DM, nullptr, 0, nullptr, 0,
        bv, HD, pAtt, DM, HD, DM, DM, 1.f);
    // 7) y = att @ Wc^T + cde @ Wf[:,256:]^T + b1
    gemm2_kernel<64, 64, 8, 4><<<dim3(DM / 64, BATCH / 64, 1), 128>>>(
        pAtt, DM, 0, pWc, DM, 0, cde, DM, Wf + DM, 2 * DM,
        pB1, 0, pY, DM, 0, DM, 2 * DM, 1.f);
    // 8) LayerNorm + ReLU -> out
    ln_relu_kernel<<<BATCH / 8, 256>>>(lg, lb, out);
}